// round 1
// baseline (speedup 1.0000x reference)
#include <cuda_runtime.h>
#include <cuda_bf16.h>
#include <math.h>

// Problem constants (fixed shapes)
#define NN 50000
#define EE 800000
#define ETOT (EE + NN)     // 850000 with self loops
#define NB 49              // ceil(NN/1024) scan blocks
#define EPS 1e-5f

// ---------------- device scratch (static, no allocation) ----------------
__device__ float d_bufA[NN * 64];
__device__ float d_bufB[NN * 64];
__device__ float d_bufC[NN * 64];
__device__ float d_es[NN * 2];
__device__ float d_ed[NN * 2];
__device__ int   d_cnt[NN];
__device__ int   d_scan[NN];
__device__ int   d_rowptr[NN + 1];
__device__ int   d_cursor[NN];
__device__ int   d_col[ETOT];
__device__ int   d_btot[NB];
__device__ int   d_boff[NB];
__device__ float d_bnacc[6 * 64];   // [layer][sum|sq][64]

// ---------------- CSR build ----------------
__global__ void zero_k() {
    int i = blockIdx.x * 256 + threadIdx.x;
    if (i < NN) d_cnt[i] = 0;
    if (i < 6 * 64) d_bnacc[i] = 0.f;
}

__global__ void count_k(const int* __restrict__ dst) {
    int i = blockIdx.x * 256 + threadIdx.x;
    if (i >= ETOT) return;
    int d = (i < EE) ? dst[i] : (i - EE);
    atomicAdd(&d_cnt[d], 1);
}

__global__ void scan1_k() {
    __shared__ int sh[1024];
    int g = blockIdx.x * 1024 + threadIdx.x;
    int v = (g < NN) ? d_cnt[g] : 0;
    sh[threadIdx.x] = v;
    __syncthreads();
    for (int off = 1; off < 1024; off <<= 1) {
        int t = (threadIdx.x >= off) ? sh[threadIdx.x - off] : 0;
        __syncthreads();
        sh[threadIdx.x] += t;
        __syncthreads();
    }
    if (g < NN) d_scan[g] = sh[threadIdx.x];
    if (threadIdx.x == 1023) d_btot[blockIdx.x] = sh[1023];
}

__global__ void scan2_k() {
    if (threadIdx.x == 0) {
        int a = 0;
#pragma unroll
        for (int b = 0; b < NB; b++) {
            int t = d_btot[b];
            d_boff[b] = a;
            a += t;
        }
    }
}

__global__ void scan3_k() {
    int i = blockIdx.x * 256 + threadIdx.x;
    if (i >= NN) return;
    int incl = d_scan[i] + d_boff[i >> 10];
    int excl = incl - d_cnt[i];
    d_rowptr[i] = excl;
    d_cursor[i] = excl;
    if (i == NN - 1) d_rowptr[NN] = incl;
}

__global__ void scatter_k(const int* __restrict__ src, const int* __restrict__ dst) {
    int i = blockIdx.x * 256 + threadIdx.x;
    if (i >= ETOT) return;
    int s, d;
    if (i < EE) { s = src[i]; d = dst[i]; }
    else        { s = i - EE; d = s; }
    int pos = atomicAdd(&d_cursor[d], 1);
    d_col[pos] = s;
}

// ---------------- GEMM: H = X @ W  (X:[N,K] W:[K,NC] H:[N,NC]) ----------------
template<int K, int NC>
__global__ void gemm_k(const float* __restrict__ X, const float* __restrict__ W,
                       float* __restrict__ Hout) {
    constexpr int CT  = NC / 4;        // col threads
    constexpr int RT  = 256 / CT;      // row threads
    constexpr int RPB = RT * 4;        // rows per block
    __shared__ float sW[K * NC];
#pragma unroll
    for (int i = threadIdx.x; i < K * NC; i += 256) sW[i] = W[i];
    __syncthreads();

    const int ct = threadIdx.x % CT;
    const int rt = threadIdx.x / CT;
    const int r0 = blockIdx.x * RPB + rt * 4;
    const int c0 = ct * 4;
    float acc[4][4] = {};

    if (r0 + 3 < NN) {
        const float* x0 = X + (size_t)r0 * K;
#pragma unroll 4
        for (int k = 0; k < K; k++) {
            float4 w = *reinterpret_cast<const float4*>(sW + k * NC + c0);
            float xv0 = x0[k];
            float xv1 = x0[K + k];
            float xv2 = x0[2 * K + k];
            float xv3 = x0[3 * K + k];
            acc[0][0] = fmaf(xv0, w.x, acc[0][0]); acc[0][1] = fmaf(xv0, w.y, acc[0][1]);
            acc[0][2] = fmaf(xv0, w.z, acc[0][2]); acc[0][3] = fmaf(xv0, w.w, acc[0][3]);
            acc[1][0] = fmaf(xv1, w.x, acc[1][0]); acc[1][1] = fmaf(xv1, w.y, acc[1][1]);
            acc[1][2] = fmaf(xv1, w.z, acc[1][2]); acc[1][3] = fmaf(xv1, w.w, acc[1][3]);
            acc[2][0] = fmaf(xv2, w.x, acc[2][0]); acc[2][1] = fmaf(xv2, w.y, acc[2][1]);
            acc[2][2] = fmaf(xv2, w.z, acc[2][2]); acc[2][3] = fmaf(xv2, w.w, acc[2][3]);
            acc[3][0] = fmaf(xv3, w.x, acc[3][0]); acc[3][1] = fmaf(xv3, w.y, acc[3][1]);
            acc[3][2] = fmaf(xv3, w.z, acc[3][2]); acc[3][3] = fmaf(xv3, w.w, acc[3][3]);
        }
    } else {
        for (int k = 0; k < K; k++) {
            float4 w = *reinterpret_cast<const float4*>(sW + k * NC + c0);
#pragma unroll
            for (int i = 0; i < 4; i++) {
                float xv = (r0 + i < NN) ? X[(size_t)(r0 + i) * K + k] : 0.f;
                acc[i][0] = fmaf(xv, w.x, acc[i][0]);
                acc[i][1] = fmaf(xv, w.y, acc[i][1]);
                acc[i][2] = fmaf(xv, w.z, acc[i][2]);
                acc[i][3] = fmaf(xv, w.w, acc[i][3]);
            }
        }
    }
#pragma unroll
    for (int i = 0; i < 4; i++) {
        if (r0 + i < NN) {
            float4 o = make_float4(acc[i][0], acc[i][1], acc[i][2], acc[i][3]);
            *reinterpret_cast<float4*>(Hout + (size_t)(r0 + i) * NC + c0) = o;
        }
    }
}

// ---------------- per-node attention logits es/ed ----------------
template<int H>
__global__ void esed_k(const float* __restrict__ Hm, const float* __restrict__ as,
                       const float* __restrict__ ad) {
    int node = blockIdx.x * (blockDim.x >> 5) + (threadIdx.x >> 5);
    if (node >= NN) return;
    int l = threadIdx.x & 31;
    if (H == 2) {
        float v0 = Hm[(size_t)node * 64 + l];
        float v1 = Hm[(size_t)node * 64 + 32 + l];
        float s0 = v0 * as[l], s1 = v1 * as[32 + l];
        float t0 = v0 * ad[l], t1 = v1 * ad[32 + l];
#pragma unroll
        for (int o = 16; o; o >>= 1) {
            s0 += __shfl_xor_sync(0xffffffffu, s0, o);
            s1 += __shfl_xor_sync(0xffffffffu, s1, o);
            t0 += __shfl_xor_sync(0xffffffffu, t0, o);
            t1 += __shfl_xor_sync(0xffffffffu, t1, o);
        }
        if (l == 0) {
            d_es[node * 2] = s0;  d_es[node * 2 + 1] = s1;
            d_ed[node * 2] = t0;  d_ed[node * 2 + 1] = t1;
        }
    } else {
        float v = Hm[(size_t)node * 32 + l];
        float s = v * as[l];
        float t = v * ad[l];
#pragma unroll
        for (int o = 16; o; o >>= 1) {
            s += __shfl_xor_sync(0xffffffffu, s, o);
            t += __shfl_xor_sync(0xffffffffu, t, o);
        }
        if (l == 0) { d_es[node] = s; d_ed[node] = t; }
    }
}

// ---------------- GAT aggregation: warp per dst node, 2-pass softmax ----------------
__device__ __forceinline__ float lrelu(float x) { return fmaxf(x, 0.2f * x); }

template<int H>
__global__ void agg_k(const float* __restrict__ Hm, const float* __restrict__ bias,
                      float* __restrict__ out) {
    int node = blockIdx.x * (blockDim.x >> 5) + (threadIdx.x >> 5);
    if (node >= NN) return;
    int l = threadIdx.x & 31;
    int beg = __ldg(&d_rowptr[node]);
    int end = __ldg(&d_rowptr[node + 1]);

    if (H == 2) {
        const float2* es2 = reinterpret_cast<const float2*>(d_es);
        float ed0 = d_ed[node * 2], ed1 = d_ed[node * 2 + 1];
        float m0 = -1e30f, m1 = -1e30f;
        for (int j = beg; j < end; j++) {
            int s = __ldg(&d_col[j]);
            float2 e = __ldg(&es2[s]);
            m0 = fmaxf(m0, lrelu(e.x + ed0));
            m1 = fmaxf(m1, lrelu(e.y + ed1));
        }
        float dn0 = 0.f, dn1 = 0.f, a0 = 0.f, a1 = 0.f;
        for (int j = beg; j < end; j++) {
            int s = __ldg(&d_col[j]);
            float2 e = __ldg(&es2[s]);
            float p0 = __expf(lrelu(e.x + ed0) - m0);
            float p1 = __expf(lrelu(e.y + ed1) - m1);
            dn0 += p0;  dn1 += p1;
            a0 = fmaf(p0, Hm[(size_t)s * 64 + l], a0);
            a1 = fmaf(p1, Hm[(size_t)s * 64 + 32 + l], a1);
        }
        out[(size_t)node * 64 + l]      = a0 / (dn0 + 1e-16f) + bias[l];
        out[(size_t)node * 64 + 32 + l] = a1 / (dn1 + 1e-16f) + bias[32 + l];
    } else {
        float edv = d_ed[node];
        float m = -1e30f;
        for (int j = beg; j < end; j++) {
            int s = __ldg(&d_col[j]);
            m = fmaxf(m, lrelu(d_es[s] + edv));
        }
        float dn = 0.f, a = 0.f;
        for (int j = beg; j < end; j++) {
            int s = __ldg(&d_col[j]);
            float p = __expf(lrelu(d_es[s] + edv) - m);
            dn += p;
            a = fmaf(p, Hm[(size_t)s * 32 + l], a);
        }
        out[(size_t)node * 32 + l] = a / (dn + 1e-16f) + bias[l];
    }
}

// ---------------- BatchNorm (training mode) + ReLU ----------------
template<int NC>
__global__ void bnstats_k(const float* __restrict__ X, float* __restrict__ acc) {
    constexpr int RPI = 256 / NC;
    int c  = threadIdx.x % NC;
    int rl = threadIdx.x / NC;
    float s = 0.f, q = 0.f;
    for (int r = blockIdx.x * RPI + rl; r < NN; r += gridDim.x * RPI) {
        float v = X[(size_t)r * NC + c];
        s += v;
        q = fmaf(v, v, q);
    }
    __shared__ float sh[256], sh2[256];
    sh[threadIdx.x] = s; sh2[threadIdx.x] = q;
    __syncthreads();
    if (rl == 0) {
#pragma unroll
        for (int i = 1; i < RPI; i++) { s += sh[i * NC + c]; q += sh2[i * NC + c]; }
        atomicAdd(&acc[c], s);
        atomicAdd(&acc[64 + c], q);
    }
}

template<int NC>
__global__ void bnapply_k(const float* __restrict__ X, const float* __restrict__ acc,
                          const float* __restrict__ g, const float* __restrict__ be,
                          float* __restrict__ Y) {
    int idx = blockIdx.x * 256 + threadIdx.x;
    if (idx >= NN * NC) return;
    int c = idx % NC;
    const float inv = 1.f / (float)NN;
    float mu  = acc[c] * inv;
    float var = fmaf(-mu, mu, acc[64 + c] * inv);
    float y = (X[idx] - mu) * rsqrtf(var + EPS) * g[c] + be[c];
    Y[idx] = fmaxf(y, 0.f);
}

// ---------------- launch ----------------
static inline int cdiv(int a, int b) { return (a + b - 1) / b; }

extern "C" void kernel_launch(void* const* d_in, const int* in_sizes, int n_in,
                              void* d_out, int out_size) {
    const float* x   = (const float*)d_in[0];
    const float* W1  = (const float*)d_in[1];
    const float* as1 = (const float*)d_in[2];
    const float* ad1 = (const float*)d_in[3];
    const float* b1  = (const float*)d_in[4];
    const float* g1  = (const float*)d_in[5];
    const float* be1 = (const float*)d_in[6];
    const float* W2  = (const float*)d_in[7];
    const float* as2 = (const float*)d_in[8];
    const float* ad2 = (const float*)d_in[9];
    const float* b2  = (const float*)d_in[10];
    const float* g2  = (const float*)d_in[11];
    const float* be2 = (const float*)d_in[12];
    const float* W3  = (const float*)d_in[13];
    const float* as3 = (const float*)d_in[14];
    const float* ad3 = (const float*)d_in[15];
    const float* b3  = (const float*)d_in[16];
    const float* g3  = (const float*)d_in[17];
    const float* be3 = (const float*)d_in[18];
    const int*   ei  = (const int*)d_in[19];
    const int* esrc = ei;
    const int* edst = ei + EE;

    float* bufA; cudaGetSymbolAddress((void**)&bufA, d_bufA);
    float* bufB; cudaGetSymbolAddress((void**)&bufB, d_bufB);
    float* bufC; cudaGetSymbolAddress((void**)&bufC, d_bufC);
    float* bnac; cudaGetSymbolAddress((void**)&bnac, d_bnacc);
    float* outp = (float*)d_out;

    // CSR build (dst identical across layers)
    zero_k<<<cdiv(NN, 256), 256>>>();
    count_k<<<cdiv(ETOT, 256), 256>>>(edst);
    scan1_k<<<NB, 1024>>>();
    scan2_k<<<1, 32>>>();
    scan3_k<<<cdiv(NN, 256), 256>>>();
    scatter_k<<<cdiv(ETOT, 256), 256>>>(esrc, edst);

    const int WPB = 8;                       // warps per block for node kernels
    const int nodeBlocks = cdiv(NN, WPB);

    // ---- layer 1: in=x[N,128] -> bufA[N,64]
    gemm_k<128, 64><<<cdiv(NN, 64), 256>>>(x, W1, bufB);
    esed_k<2><<<nodeBlocks, 256>>>(bufB, as1, ad1);
    agg_k<2><<<nodeBlocks, 256>>>(bufB, b1, bufC);
    bnstats_k<64><<<148, 256>>>(bufC, bnac + 0 * 128);
    bnapply_k<64><<<cdiv(NN * 64, 256), 256>>>(bufC, bnac + 0 * 128, g1, be1, bufA);

    // ---- layer 2: bufA[N,64] -> bufA[N,64]
    gemm_k<64, 64><<<cdiv(NN, 64), 256>>>(bufA, W2, bufB);
    esed_k<2><<<nodeBlocks, 256>>>(bufB, as2, ad2);
    agg_k<2><<<nodeBlocks, 256>>>(bufB, b2, bufC);
    bnstats_k<64><<<148, 256>>>(bufC, bnac + 1 * 128);
    bnapply_k<64><<<cdiv(NN * 64, 256), 256>>>(bufC, bnac + 1 * 128, g2, be2, bufA);

    // ---- layer 3: bufA[N,64] -> out[N,32] (heads=1, concat=False == identity mean)
    gemm_k<64, 32><<<cdiv(NN, 128), 256>>>(bufA, W3, bufB);
    esed_k<1><<<nodeBlocks, 256>>>(bufB, as3, ad3);
    agg_k<1><<<nodeBlocks, 256>>>(bufB, b3, bufC);
    bnstats_k<32><<<148, 256>>>(bufC, bnac + 2 * 128);
    bnapply_k<32><<<cdiv(NN * 32, 256), 256>>>(bufC, bnac + 2 * 128, g3, be3, outp);
}

// round 2
// speedup vs baseline: 1.4529x; 1.4529x over previous
#include <cuda_runtime.h>
#include <cuda_bf16.h>
#include <math.h>

#define NN 50000
#define EE 800000
#define ETOT (EE + NN)
#define NB 49              // ceil(NN/1024)
#define EPS 1e-5f

// ---------------- device scratch ----------------
__device__ float d_bufA[NN * 64];
__device__ float d_bufB[NN * 64];
__device__ float d_bufC[NN * 64];
__device__ float d_es[NN * 2];
__device__ float d_ed[NN * 2];
__device__ int   d_cnt[NN];
__device__ int   d_scan[NN];
__device__ int   d_rowptr[NN + 1];
__device__ int   d_cursor[NN];
__device__ int   d_col[ETOT];
__device__ int   d_btot[NB];
__device__ int   d_boff[NB];
__device__ float d_bnacc[3 * 128];   // per layer: [sum(NC) | sumsq(NC)]
__device__ float d_bns[3 * 128];     // per layer: [scale(NC) | shift(NC)]
__device__ int   d_bnctr[3];

// ---------------- init ----------------
__global__ void zero_k() {
    int i = blockIdx.x * 256 + threadIdx.x;
    if (i < NN) d_cnt[i] = 0;
    if (i < 3 * 128) d_bnacc[i] = 0.f;
    if (i < 3) d_bnctr[i] = 0;
}

__global__ void count_k(const int* __restrict__ dst) {
    int i = blockIdx.x * 256 + threadIdx.x;
    if (i >= ETOT) return;
    int d = (i < EE) ? dst[i] : (i - EE);
    atomicAdd(&d_cnt[d], 1);
}

// warp-shuffle block scan (inclusive)
__global__ void scan1_k() {
    __shared__ int wsum[32];
    int g = blockIdx.x * 1024 + threadIdx.x;
    int lane = threadIdx.x & 31, wid = threadIdx.x >> 5;
    int v = (g < NN) ? d_cnt[g] : 0;
    int x = v;
#pragma unroll
    for (int o = 1; o < 32; o <<= 1) {
        int t = __shfl_up_sync(0xffffffffu, x, o);
        if (lane >= o) x += t;
    }
    if (lane == 31) wsum[wid] = x;
    __syncthreads();
    if (wid == 0) {
        int w = wsum[lane];
#pragma unroll
        for (int o = 1; o < 32; o <<= 1) {
            int t = __shfl_up_sync(0xffffffffu, w, o);
            if (lane >= o) w += t;
        }
        wsum[lane] = w;
    }
    __syncthreads();
    int incl = x + (wid ? wsum[wid - 1] : 0);
    if (g < NN) d_scan[g] = incl;
    if (threadIdx.x == 1023) d_btot[blockIdx.x] = incl;
}

__global__ void scan2_k() {   // 64 threads, NB=49
    int t = threadIdx.x;
    int lane = t & 31, w = t >> 5;
    int v = (t < NB) ? d_btot[t] : 0;
    int x = v;
#pragma unroll
    for (int o = 1; o < 32; o <<= 1) {
        int s = __shfl_up_sync(0xffffffffu, x, o);
        if (lane >= o) x += s;
    }
    __shared__ int s0;
    if (w == 0 && lane == 31) s0 = x;
    __syncthreads();
    int incl = x + (w ? s0 : 0);
    if (t < NB) d_boff[t] = incl - v;   // exclusive
}

__global__ void scan3_k() {
    int i = blockIdx.x * 256 + threadIdx.x;
    if (i >= NN) return;
    int incl = d_scan[i] + d_boff[i >> 10];
    int excl = incl - d_cnt[i];
    d_rowptr[i] = excl;
    d_cursor[i] = excl;
    if (i == NN - 1) d_rowptr[NN] = incl;
}

__global__ void scatter_k(const int* __restrict__ src, const int* __restrict__ dst) {
    int i = blockIdx.x * 256 + threadIdx.x;
    if (i >= ETOT) return;
    int s, d;
    if (i < EE) { s = src[i]; d = dst[i]; }
    else        { s = i - EE; d = s; }
    int pos = atomicAdd(&d_cursor[d], 1);
    d_col[pos] = s;
}

// ---------------- fused GEMM + optional BN/ReLU on input + es/ed epilogue ----------
// H = relu(bn(X)) @ W   (BN optional), then es[i,h]=sum_d h*a_src, ed likewise.
template<int K, int NC, bool BN, int H>
__global__ void __launch_bounds__(256) gemm_k(
    const float* __restrict__ X, const float* __restrict__ W,
    const float* __restrict__ asv, const float* __restrict__ adv,
    const float* __restrict__ bns, float* __restrict__ Hout)
{
    constexpr int CT  = NC / 4;
    constexpr int RT  = 256 / CT;
    constexpr int RPB = RT * 4;
    __shared__ float sW[64 * NC];
    __shared__ float sX[RPB * 64];
    __shared__ float sS[BN ? K : 1];
    __shared__ float sT[BN ? K : 1];

    if (BN) {
        for (int i = threadIdx.x; i < K; i += 256) {
            sS[i] = bns[i];
            sT[i] = bns[K + i];
        }
    }
    const int ct = threadIdx.x % CT;
    const int rt = threadIdx.x / CT;
    const int r0 = blockIdx.x * RPB;
    const int row0 = rt * 4;
    float acc[4][4] = {};

    for (int kt = 0; kt < K; kt += 64) {
        __syncthreads();
        // stage W chunk [64 x NC]
#pragma unroll
        for (int i = threadIdx.x; i < 64 * NC / 4; i += 256) {
            int kr = i / (NC / 4), c4 = i % (NC / 4);
            reinterpret_cast<float4*>(sW)[i] =
                reinterpret_cast<const float4*>(W + (size_t)(kt + kr) * NC)[c4];
        }
        // stage X chunk [RPB x 64] with optional BN+ReLU
#pragma unroll
        for (int i = threadIdx.x; i < RPB * 16; i += 256) {
            int r = i >> 4, c4 = i & 15;
            int gr = r0 + r;
            float4 v = make_float4(0.f, 0.f, 0.f, 0.f);
            if (gr < NN)
                v = reinterpret_cast<const float4*>(X + (size_t)gr * K + kt)[c4];
            if (BN) {
                int kk = kt + c4 * 4;
                v.x = fmaxf(fmaf(v.x, sS[kk + 0], sT[kk + 0]), 0.f);
                v.y = fmaxf(fmaf(v.y, sS[kk + 1], sT[kk + 1]), 0.f);
                v.z = fmaxf(fmaf(v.z, sS[kk + 2], sT[kk + 2]), 0.f);
                v.w = fmaxf(fmaf(v.w, sS[kk + 3], sT[kk + 3]), 0.f);
            }
            reinterpret_cast<float4*>(sX)[i] = v;
        }
        __syncthreads();
#pragma unroll 8
        for (int k = 0; k < 64; k += 4) {
            float4 wv0 = *reinterpret_cast<const float4*>(sW + (k + 0) * NC + ct * 4);
            float4 wv1 = *reinterpret_cast<const float4*>(sW + (k + 1) * NC + ct * 4);
            float4 wv2 = *reinterpret_cast<const float4*>(sW + (k + 2) * NC + ct * 4);
            float4 wv3 = *reinterpret_cast<const float4*>(sW + (k + 3) * NC + ct * 4);
#pragma unroll
            for (int i = 0; i < 4; i++) {
                float4 xv = *reinterpret_cast<const float4*>(sX + (row0 + i) * 64 + k);
                acc[i][0] = fmaf(xv.x, wv0.x, acc[i][0]);
                acc[i][1] = fmaf(xv.x, wv0.y, acc[i][1]);
                acc[i][2] = fmaf(xv.x, wv0.z, acc[i][2]);
                acc[i][3] = fmaf(xv.x, wv0.w, acc[i][3]);
                acc[i][0] = fmaf(xv.y, wv1.x, acc[i][0]);
                acc[i][1] = fmaf(xv.y, wv1.y, acc[i][1]);
                acc[i][2] = fmaf(xv.y, wv1.z, acc[i][2]);
                acc[i][3] = fmaf(xv.y, wv1.w, acc[i][3]);
                acc[i][0] = fmaf(xv.z, wv2.x, acc[i][0]);
                acc[i][1] = fmaf(xv.z, wv2.y, acc[i][1]);
                acc[i][2] = fmaf(xv.z, wv2.z, acc[i][2]);
                acc[i][3] = fmaf(xv.z, wv2.w, acc[i][3]);
                acc[i][0] = fmaf(xv.w, wv3.x, acc[i][0]);
                acc[i][1] = fmaf(xv.w, wv3.y, acc[i][1]);
                acc[i][2] = fmaf(xv.w, wv3.z, acc[i][2]);
                acc[i][3] = fmaf(xv.w, wv3.w, acc[i][3]);
            }
        }
    }

    // epilogue: store H + fused es/ed (shfl-reduce over the 8 ct-lanes of each head)
    float4 a_s = *reinterpret_cast<const float4*>(asv + ct * 4);
    float4 a_d = *reinterpret_cast<const float4*>(adv + ct * 4);
#pragma unroll
    for (int i = 0; i < 4; i++) {
        int gr = r0 + row0 + i;
        float ps = acc[i][0] * a_s.x + acc[i][1] * a_s.y + acc[i][2] * a_s.z + acc[i][3] * a_s.w;
        float pd = acc[i][0] * a_d.x + acc[i][1] * a_d.y + acc[i][2] * a_d.z + acc[i][3] * a_d.w;
        ps += __shfl_xor_sync(0xffffffffu, ps, 1);
        pd += __shfl_xor_sync(0xffffffffu, pd, 1);
        ps += __shfl_xor_sync(0xffffffffu, ps, 2);
        pd += __shfl_xor_sync(0xffffffffu, pd, 2);
        ps += __shfl_xor_sync(0xffffffffu, ps, 4);
        pd += __shfl_xor_sync(0xffffffffu, pd, 4);
        if (gr < NN) {
            float4 o = make_float4(acc[i][0], acc[i][1], acc[i][2], acc[i][3]);
            *reinterpret_cast<float4*>(Hout + (size_t)gr * NC + ct * 4) = o;
            if ((ct & 7) == 0) {
                int head = (H == 2) ? (ct >> 3) : 0;
                d_es[gr * H + head] = ps;
                d_ed[gr * H + head] = pd;
            }
        }
    }
}

// ---------------- GAT aggregation: warp per dst node, single pass (no max) ---------
__device__ __forceinline__ float lrelu(float x) { return fmaxf(x, 0.2f * x); }

template<int H>
__global__ void __launch_bounds__(256) agg_k(const float* __restrict__ Hm,
                                             const float* __restrict__ bias,
                                             float* __restrict__ out) {
    int node = blockIdx.x * 8 + (threadIdx.x >> 5);
    if (node >= NN) return;
    int l = threadIdx.x & 31;
    int beg = __ldg(&d_rowptr[node]);
    int end = __ldg(&d_rowptr[node + 1]);

    if (H == 2) {
        const float2 edv = reinterpret_cast<const float2*>(d_ed)[node];
        const float2* es2 = reinterpret_cast<const float2*>(d_es);
        float dn0 = 0.f, dn1 = 0.f, a0 = 0.f, a1 = 0.f;
#pragma unroll 4
        for (int j = beg; j < end; j++) {
            int s = __ldg(&d_col[j]);
            float2 e = __ldg(&es2[s]);
            float p0 = __expf(lrelu(e.x + edv.x));
            float p1 = __expf(lrelu(e.y + edv.y));
            const float* hr = Hm + (size_t)s * 64;
            dn0 += p0;  dn1 += p1;
            a0 = fmaf(p0, __ldg(hr + l), a0);
            a1 = fmaf(p1, __ldg(hr + 32 + l), a1);
        }
        out[(size_t)node * 64 + l]      = a0 / (dn0 + 1e-16f) + bias[l];
        out[(size_t)node * 64 + 32 + l] = a1 / (dn1 + 1e-16f) + bias[32 + l];
    } else {
        float edv = d_ed[node];
        float dn = 0.f, a = 0.f;
#pragma unroll 4
        for (int j = beg; j < end; j++) {
            int s = __ldg(&d_col[j]);
            float p = __expf(lrelu(__ldg(&d_es[s]) + edv));
            dn += p;
            a = fmaf(p, __ldg(Hm + (size_t)s * 32 + l), a);
        }
        out[(size_t)node * 32 + l] = a / (dn + 1e-16f) + bias[l];
    }
}

// ---------------- BatchNorm stats + finalize (scale/shift) ----------------
template<int NC>
__global__ void __launch_bounds__(256) bnstats_k(const float* __restrict__ X,
                                                 float* __restrict__ acc,
                                                 const float* __restrict__ g,
                                                 const float* __restrict__ be,
                                                 float* __restrict__ bns, int layer) {
    constexpr int RPI = 256 / NC;
    int c  = threadIdx.x % NC;
    int rl = threadIdx.x / NC;
    float s = 0.f, q = 0.f;
    for (int r = blockIdx.x * RPI + rl; r < NN; r += gridDim.x * RPI) {
        float v = X[(size_t)r * NC + c];
        s += v;
        q = fmaf(v, v, q);
    }
    __shared__ float sh[256], sh2[256];
    __shared__ bool isLast;
    sh[threadIdx.x] = s;  sh2[threadIdx.x] = q;
    __syncthreads();
    if (rl == 0) {
#pragma unroll
        for (int i = 1; i < RPI; i++) { s += sh[i * NC + c]; q += sh2[i * NC + c]; }
        atomicAdd(&acc[c], s);
        atomicAdd(&acc[NC + c], q);
    }
    __threadfence();
    __syncthreads();
    if (threadIdx.x == 0)
        isLast = (atomicAdd(&d_bnctr[layer], 1) == (int)gridDim.x - 1);
    __syncthreads();
    if (isLast && threadIdx.x < NC) {
        float sum = atomicAdd(&acc[threadIdx.x], 0.f);        // L2 reads
        float sq  = atomicAdd(&acc[NC + threadIdx.x], 0.f);
        float mu  = sum * (1.f / NN);
        float var = fmaf(-mu, mu, sq * (1.f / NN));
        float sc  = rsqrtf(var + EPS) * g[threadIdx.x];
        bns[threadIdx.x]      = sc;
        bns[NC + threadIdx.x] = be[threadIdx.x] - mu * sc;
    }
}

// final layer BN apply + ReLU -> out
__global__ void bnapply3_k(const float* __restrict__ X, const float* __restrict__ bns,
                           float* __restrict__ Y) {
    int idx = blockIdx.x * 256 + threadIdx.x;
    if (idx >= NN * 32) return;
    int c = idx & 31;
    Y[idx] = fmaxf(fmaf(X[idx], bns[c], bns[32 + c]), 0.f);
}

// ---------------- launch ----------------
static inline int cdiv(int a, int b) { return (a + b - 1) / b; }

extern "C" void kernel_launch(void* const* d_in, const int* in_sizes, int n_in,
                              void* d_out, int out_size) {
    const float* x   = (const float*)d_in[0];
    const float* W1  = (const float*)d_in[1];
    const float* as1 = (const float*)d_in[2];
    const float* ad1 = (const float*)d_in[3];
    const float* b1  = (const float*)d_in[4];
    const float* g1  = (const float*)d_in[5];
    const float* be1 = (const float*)d_in[6];
    const float* W2  = (const float*)d_in[7];
    const float* as2 = (const float*)d_in[8];
    const float* ad2 = (const float*)d_in[9];
    const float* b2  = (const float*)d_in[10];
    const float* g2  = (const float*)d_in[11];
    const float* be2 = (const float*)d_in[12];
    const float* W3  = (const float*)d_in[13];
    const float* as3 = (const float*)d_in[14];
    const float* ad3 = (const float*)d_in[15];
    const float* b3  = (const float*)d_in[16];
    const float* g3  = (const float*)d_in[17];
    const float* be3 = (const float*)d_in[18];
    const int*   ei  = (const int*)d_in[19];
    const int* esrc = ei;
    const int* edst = ei + EE;

    float* bufA; cudaGetSymbolAddress((void**)&bufA, d_bufA);
    float* bufB; cudaGetSymbolAddress((void**)&bufB, d_bufB);
    float* bufC; cudaGetSymbolAddress((void**)&bufC, d_bufC);
    float* bnac; cudaGetSymbolAddress((void**)&bnac, d_bnacc);
    float* bns;  cudaGetSymbolAddress((void**)&bns,  d_bns);
    float* outp = (float*)d_out;

    // CSR build (dst identical across layers)
    zero_k<<<cdiv(NN, 256), 256>>>();
    count_k<<<cdiv(ETOT, 256), 256>>>(edst);
    scan1_k<<<NB, 1024>>>();
    scan2_k<<<1, 64>>>();
    scan3_k<<<cdiv(NN, 256), 256>>>();
    scatter_k<<<cdiv(ETOT, 256), 256>>>(esrc, edst);

    const int nodeBlocks = cdiv(NN, 8);

    // layer 1
    gemm_k<128, 64, false, 2><<<cdiv(NN, 64), 256>>>(x, W1, as1, ad1, nullptr, bufB);
    agg_k<2><<<nodeBlocks, 256>>>(bufB, b1, bufC);
    bnstats_k<64><<<148, 256>>>(bufC, bnac + 0 * 128, g1, be1, bns + 0 * 128, 0);

    // layer 2 (BN+ReLU fused into X staging)
    gemm_k<64, 64, true, 2><<<cdiv(NN, 64), 256>>>(bufC, W2, as2, ad2, bns + 0 * 128, bufB);
    agg_k<2><<<nodeBlocks, 256>>>(bufB, b2, bufC);
    bnstats_k<64><<<148, 256>>>(bufC, bnac + 1 * 128, g2, be2, bns + 1 * 128, 1);

    // layer 3
    gemm_k<64, 32, true, 1><<<cdiv(NN, 128), 256>>>(bufC, W3, as3, ad3, bns + 1 * 128, bufA);
    agg_k<1><<<nodeBlocks, 256>>>(bufA, b3, bufC);
    bnstats_k<32><<<148, 256>>>(bufC, bnac + 2 * 128, g3, be3, bns + 2 * 128, 2);
    bnapply3_k<<<cdiv(NN * 32, 256), 256>>>(bufC, bns + 2 * 128, outp);
}

// round 4
// speedup vs baseline: 1.8189x; 1.2519x over previous
#include <cuda_runtime.h>
#include <cuda_bf16.h>
#include <math.h>

#define NN 50000
#define EE 800000
#define ETOT (EE + NN)
#define NB 49              // ceil(NN/1024)
#define EPS 1e-5f

// ---------------- device scratch ----------------
__device__ float d_bufA[NN * 64];
__device__ float d_bufB[NN * 64];
__device__ float d_bufC[NN * 64];
__device__ float d_es[NN * 2];
__device__ float d_ed[NN * 2];
__device__ int   d_cnt[NN];
__device__ int   d_scan[NN];
__device__ int   d_rowptr[NN + 1];
__device__ int   d_cursor[NN];
__device__ int   d_col[ETOT];
__device__ int   d_btot[NB];
__device__ int   d_boff[NB];
__device__ float d_bnacc[320];   // L1:[sum64|sq64] L2:[sum64|sq64] L3:[sum32|sq32]

// ---------------- init ----------------
__global__ void zero_k() {
    int i = blockIdx.x * 256 + threadIdx.x;
    if (i < NN) d_cnt[i] = 0;
    if (i < 320) d_bnacc[i] = 0.f;
}

__global__ void count_k(const int* __restrict__ dst) {
    int i = blockIdx.x * 256 + threadIdx.x;
    if (i >= ETOT) return;
    int d = (i < EE) ? __ldg(&dst[i]) : (i - EE);
    atomicAdd(&d_cnt[d], 1);
}

__global__ void scan1_k() {
    __shared__ int wsum[32];
    int g = blockIdx.x * 1024 + threadIdx.x;
    int lane = threadIdx.x & 31, wid = threadIdx.x >> 5;
    int v = (g < NN) ? d_cnt[g] : 0;
    int x = v;
#pragma unroll
    for (int o = 1; o < 32; o <<= 1) {
        int t = __shfl_up_sync(0xffffffffu, x, o);
        if (lane >= o) x += t;
    }
    if (lane == 31) wsum[wid] = x;
    __syncthreads();
    if (wid == 0) {
        int w = wsum[lane];
#pragma unroll
        for (int o = 1; o < 32; o <<= 1) {
            int t = __shfl_up_sync(0xffffffffu, w, o);
            if (lane >= o) w += t;
        }
        wsum[lane] = w;
    }
    __syncthreads();
    int incl = x + (wid ? wsum[wid - 1] : 0);
    if (g < NN) d_scan[g] = incl;
    if (threadIdx.x == 1023) d_btot[blockIdx.x] = incl;
}

__global__ void scan2_k() {   // 64 threads, NB=49
    int t = threadIdx.x;
    int lane = t & 31, w = t >> 5;
    int v = (t < NB) ? d_btot[t] : 0;
    int x = v;
#pragma unroll
    for (int o = 1; o < 32; o <<= 1) {
        int s = __shfl_up_sync(0xffffffffu, x, o);
        if (lane >= o) x += s;
    }
    __shared__ int s0;
    if (w == 0 && lane == 31) s0 = x;
    __syncthreads();
    int incl = x + (w ? s0 : 0);
    if (t < NB) d_boff[t] = incl - v;
}

__global__ void scan3_k() {
    int i = blockIdx.x * 256 + threadIdx.x;
    if (i >= NN) return;
    int incl = d_scan[i] + d_boff[i >> 10];
    int excl = incl - d_cnt[i];
    d_rowptr[i] = excl;
    d_cursor[i] = excl;
    if (i == NN - 1) d_rowptr[NN] = incl;
}

__global__ void scatter_k(const int* __restrict__ src, const int* __restrict__ dst) {
    int i = blockIdx.x * 256 + threadIdx.x;
    if (i >= ETOT) return;
    int s, d;
    if (i < EE) { s = __ldg(&src[i]); d = __ldg(&dst[i]); }
    else        { s = i - EE; d = s; }
    int pos = atomicAdd(&d_cursor[d], 1);
    d_col[pos] = s;
}

// ------- fused GEMM (R2-proven scalar core) + BN-from-acc input + es/ed epilogue ----
// H = relu(bn(X)) @ W (BN optional); es/ed via shfl reduce over head col-lanes.
template<int K, int NC, bool BN, int H>
__global__ void __launch_bounds__(256) gemm_k(
    const float* __restrict__ X, const float* __restrict__ W,
    const float* __restrict__ asv, const float* __restrict__ adv,
    const float* __restrict__ accIn, const float* __restrict__ g,
    const float* __restrict__ be, float* __restrict__ Hout)
{
    constexpr int CT  = NC / 4;        // 16 (NC=64) or 8 (NC=32)
    constexpr int RT  = 256 / CT;      // 16 or 32
    constexpr int RPB = RT * 4;        // 64 or 128 rows per block
    __shared__ float sW[64 * NC];
    __shared__ float sX[RPB * 64];
    __shared__ float sS[BN ? K : 1];
    __shared__ float sT[BN ? K : 1];

    if (BN) {
        if (threadIdx.x < K) {
            float mu  = accIn[threadIdx.x] * (1.f / NN);
            float var = fmaf(-mu, mu, accIn[K + threadIdx.x] * (1.f / NN));
            float sc  = rsqrtf(var + EPS) * g[threadIdx.x];
            sS[threadIdx.x] = sc;
            sT[threadIdx.x] = be[threadIdx.x] - mu * sc;
        }
    }
    const int ct = threadIdx.x % CT;
    const int rt = threadIdx.x / CT;
    const int r0 = blockIdx.x * RPB;
    const int row0 = rt * 4;
    float acc[4][4] = {};

    for (int kt = 0; kt < K; kt += 64) {
        __syncthreads();
        // stage W chunk [64 x NC]
#pragma unroll
        for (int i = threadIdx.x; i < 64 * NC / 4; i += 256) {
            reinterpret_cast<float4*>(sW)[i] =
                __ldg(reinterpret_cast<const float4*>(W) + (size_t)kt * (NC / 4) + i);
        }
        // stage X chunk [RPB x 64] with optional BN+ReLU
#pragma unroll
        for (int i = threadIdx.x; i < RPB * 16; i += 256) {
            int r = i >> 4, c4 = i & 15;
            int gr = r0 + r;
            float4 v = make_float4(0.f, 0.f, 0.f, 0.f);
            if (gr < NN)
                v = *reinterpret_cast<const float4*>(X + (size_t)gr * K + kt + c4 * 4);
            if (BN) {
                int kk = kt + c4 * 4;
                v.x = fmaxf(fmaf(v.x, sS[kk + 0], sT[kk + 0]), 0.f);
                v.y = fmaxf(fmaf(v.y, sS[kk + 1], sT[kk + 1]), 0.f);
                v.z = fmaxf(fmaf(v.z, sS[kk + 2], sT[kk + 2]), 0.f);
                v.w = fmaxf(fmaf(v.w, sS[kk + 3], sT[kk + 3]), 0.f);
            }
            reinterpret_cast<float4*>(sX)[i] = v;
        }
        __syncthreads();
#pragma unroll 8
        for (int k = 0; k < 64; k += 4) {
            float4 wv0 = *reinterpret_cast<const float4*>(sW + (k + 0) * NC + ct * 4);
            float4 wv1 = *reinterpret_cast<const float4*>(sW + (k + 1) * NC + ct * 4);
            float4 wv2 = *reinterpret_cast<const float4*>(sW + (k + 2) * NC + ct * 4);
            float4 wv3 = *reinterpret_cast<const float4*>(sW + (k + 3) * NC + ct * 4);
#pragma unroll
            for (int i = 0; i < 4; i++) {
                float4 xv = *reinterpret_cast<const float4*>(sX + (row0 + i) * 64 + k);
                acc[i][0] = fmaf(xv.x, wv0.x, acc[i][0]);
                acc[i][1] = fmaf(xv.x, wv0.y, acc[i][1]);
                acc[i][2] = fmaf(xv.x, wv0.z, acc[i][2]);
                acc[i][3] = fmaf(xv.x, wv0.w, acc[i][3]);
                acc[i][0] = fmaf(xv.y, wv1.x, acc[i][0]);
                acc[i][1] = fmaf(xv.y, wv1.y, acc[i][1]);
                acc[i][2] = fmaf(xv.y, wv1.z, acc[i][2]);
                acc[i][3] = fmaf(xv.y, wv1.w, acc[i][3]);
                acc[i][0] = fmaf(xv.z, wv2.x, acc[i][0]);
                acc[i][1] = fmaf(xv.z, wv2.y, acc[i][1]);
                acc[i][2] = fmaf(xv.z, wv2.z, acc[i][2]);
                acc[i][3] = fmaf(xv.z, wv2.w, acc[i][3]);
                acc[i][0] = fmaf(xv.w, wv3.x, acc[i][0]);
                acc[i][1] = fmaf(xv.w, wv3.y, acc[i][1]);
                acc[i][2] = fmaf(xv.w, wv3.z, acc[i][2]);
                acc[i][3] = fmaf(xv.w, wv3.w, acc[i][3]);
            }
        }
    }

    // epilogue: store H + fused es/ed (shfl-reduce over the 8 ct-lanes of each head)
    float4 a_s = *reinterpret_cast<const float4*>(asv + ct * 4);
    float4 a_d = *reinterpret_cast<const float4*>(adv + ct * 4);
#pragma unroll
    for (int i = 0; i < 4; i++) {
        int gr = r0 + row0 + i;
        float ps = acc[i][0] * a_s.x + acc[i][1] * a_s.y + acc[i][2] * a_s.z + acc[i][3] * a_s.w;
        float pd = acc[i][0] * a_d.x + acc[i][1] * a_d.y + acc[i][2] * a_d.z + acc[i][3] * a_d.w;
        ps += __shfl_xor_sync(0xffffffffu, ps, 1);
        pd += __shfl_xor_sync(0xffffffffu, pd, 1);
        ps += __shfl_xor_sync(0xffffffffu, ps, 2);
        pd += __shfl_xor_sync(0xffffffffu, pd, 2);
        ps += __shfl_xor_sync(0xffffffffu, ps, 4);
        pd += __shfl_xor_sync(0xffffffffu, pd, 4);
        if (gr < NN) {
            float4 o = make_float4(acc[i][0], acc[i][1], acc[i][2], acc[i][3]);
            *reinterpret_cast<float4*>(Hout + (size_t)gr * NC + ct * 4) = o;
            if ((ct & 7) == 0) {
                int head = (H == 2) ? (ct >> 3) : 0;
                d_es[gr * H + head] = ps;
                d_ed[gr * H + head] = pd;
            }
        }
    }
}

// -------- GAT aggregation (warp/node) + fused BN stats (smem tree + atomics) ------
__device__ __forceinline__ float lrelu(float x) { return fmaxf(x, 0.2f * x); }

template<int H>
__global__ void __launch_bounds__(512) agg_k(const float* __restrict__ Hm,
                                             const float* __restrict__ bias,
                                             float* __restrict__ out,
                                             float* __restrict__ accOut) {
    __shared__ float red[16][128];
    int w = threadIdx.x >> 5;
    int l = threadIdx.x & 31;
    int node = blockIdx.x * 16 + w;

    if (H == 2) {
        float o0 = 0.f, o1 = 0.f;
        if (node < NN) {
            int beg = __ldg(&d_rowptr[node]);
            int end = __ldg(&d_rowptr[node + 1]);
            const float2 edv = reinterpret_cast<const float2*>(d_ed)[node];
            const float2* es2 = reinterpret_cast<const float2*>(d_es);
            float dn0 = 0.f, dn1 = 0.f, a0 = 0.f, a1 = 0.f;
#pragma unroll 4
            for (int j = beg; j < end; j++) {
                int s = __ldg(&d_col[j]);
                float2 e = __ldg(&es2[s]);
                float p0 = __expf(lrelu(e.x + edv.x));
                float p1 = __expf(lrelu(e.y + edv.y));
                const float* hr = Hm + (size_t)s * 64;
                dn0 += p0; dn1 += p1;
                a0 = fmaf(p0, __ldg(hr + l), a0);
                a1 = fmaf(p1, __ldg(hr + 32 + l), a1);
            }
            o0 = a0 / (dn0 + 1e-16f) + __ldg(bias + l);
            o1 = a1 / (dn1 + 1e-16f) + __ldg(bias + 32 + l);
            out[(size_t)node * 64 + l]      = o0;
            out[(size_t)node * 64 + 32 + l] = o1;
        }
        red[w][l]      = o0;
        red[w][32 + l] = o1;
        red[w][64 + l] = o0 * o0;
        red[w][96 + l] = o1 * o1;
        __syncthreads();
        if (threadIdx.x < 128) {
            float s = 0.f;
#pragma unroll
            for (int i = 0; i < 16; i++) s += red[i][threadIdx.x];
            atomicAdd(&accOut[threadIdx.x], s);
        }
    } else {
        float o = 0.f;
        if (node < NN) {
            int beg = __ldg(&d_rowptr[node]);
            int end = __ldg(&d_rowptr[node + 1]);
            float edv = d_ed[node];
            float dn = 0.f, a = 0.f;
#pragma unroll 4
            for (int j = beg; j < end; j++) {
                int s = __ldg(&d_col[j]);
                float p = __expf(lrelu(__ldg(&d_es[s]) + edv));
                dn += p;
                a = fmaf(p, __ldg(Hm + (size_t)s * 32 + l), a);
            }
            o = a / (dn + 1e-16f) + __ldg(bias + l);
            out[(size_t)node * 32 + l] = o;
        }
        red[w][l]      = o;
        red[w][32 + l] = o * o;
        __syncthreads();
        if (threadIdx.x < 64) {
            float s = 0.f;
#pragma unroll
            for (int i = 0; i < 16; i++) s += red[i][threadIdx.x];
            atomicAdd(&accOut[threadIdx.x], s);
        }
    }
}

// final BN apply + ReLU -> out (stats direct from acc)
__global__ void bnapply3_k(const float* __restrict__ X, const float* __restrict__ acc,
                           const float* __restrict__ g, const float* __restrict__ be,
                           float* __restrict__ Y) {
    int idx = blockIdx.x * 256 + threadIdx.x;
    if (idx >= NN * 32) return;
    int c = idx & 31;
    float mu  = acc[c] * (1.f / NN);
    float var = fmaf(-mu, mu, acc[32 + c] * (1.f / NN));
    float y = (X[idx] - mu) * rsqrtf(var + EPS) * g[c] + be[c];
    Y[idx] = fmaxf(y, 0.f);
}

// ---------------- launch ----------------
static inline int cdiv(int a, int b) { return (a + b - 1) / b; }

extern "C" void kernel_launch(void* const* d_in, const int* in_sizes, int n_in,
                              void* d_out, int out_size) {
    const float* x   = (const float*)d_in[0];
    const float* W1  = (const float*)d_in[1];
    const float* as1 = (const float*)d_in[2];
    const float* ad1 = (const float*)d_in[3];
    const float* b1  = (const float*)d_in[4];
    const float* g1  = (const float*)d_in[5];
    const float* be1 = (const float*)d_in[6];
    const float* W2  = (const float*)d_in[7];
    const float* as2 = (const float*)d_in[8];
    const float* ad2 = (const float*)d_in[9];
    const float* b2  = (const float*)d_in[10];
    const float* g2  = (const float*)d_in[11];
    const float* be2 = (const float*)d_in[12];
    const float* W3  = (const float*)d_in[13];
    const float* as3 = (const float*)d_in[14];
    const float* ad3 = (const float*)d_in[15];
    const float* b3  = (const float*)d_in[16];
    const float* g3  = (const float*)d_in[17];
    const float* be3 = (const float*)d_in[18];
    const int*   ei  = (const int*)d_in[19];
    const int* esrc = ei;
    const int* edst = ei + EE;

    float* bufA; cudaGetSymbolAddress((void**)&bufA, d_bufA);
    float* bufB; cudaGetSymbolAddress((void**)&bufB, d_bufB);
    float* bufC; cudaGetSymbolAddress((void**)&bufC, d_bufC);
    float* bnac; cudaGetSymbolAddress((void**)&bnac, d_bnacc);
    float* outp = (float*)d_out;

    const int aggBlocks = cdiv(NN, 16);   // 3125

    // CSR build; gemm1 interleaved (independent of CSR)
    zero_k<<<cdiv(NN, 256), 256>>>();
    count_k<<<cdiv(ETOT, 256), 256>>>(edst);
    scan1_k<<<NB, 1024>>>();
    gemm_k<128, 64, false, 2><<<cdiv(NN, 64), 256>>>(
        x, W1, as1, ad1, nullptr, nullptr, nullptr, bufB);
    scan2_k<<<1, 64>>>();
    scan3_k<<<cdiv(NN, 256), 256>>>();
    scatter_k<<<cdiv(ETOT, 256), 256>>>(esrc, edst);

    // layer 1 aggregation (+BN1 stats)
    agg_k<2><<<aggBlocks, 512>>>(bufB, b1, bufC, bnac + 0);

    // layer 2 (BN1+ReLU fused into X staging)
    gemm_k<64, 64, true, 2><<<cdiv(NN, 64), 256>>>(
        bufC, W2, as2, ad2, bnac + 0, g1, be1, bufB);
    agg_k<2><<<aggBlocks, 512>>>(bufB, b2, bufC, bnac + 128);

    // layer 3 (BN2+ReLU fused into X staging)
    gemm_k<64, 32, true, 1><<<cdiv(NN, 128), 256>>>(
        bufC, W3, as3, ad3, bnac + 128, g2, be2, bufA);
    agg_k<1><<<aggBlocks, 512>>>(bufA, b3, bufC, bnac + 256);
    bnapply3_k<<<cdiv(NN * 32, 256), 256>>>(bufC, bnac + 256, g3, be3, outp);
}